// round 6
// baseline (speedup 1.0000x reference)
#include <cuda_runtime.h>
#include <cuda_bf16.h>
#include <mma.h>
#include <math.h>
#include <cstdint>
#include <stdint.h>

using namespace nvcuda;

// Problem dims
#define Bb   8192
#define Tt   8
#define Vv   65
#define Cc   512
#define Hh   8
#define HSs  64
#define Ll   6
#define DFFd 2048
#define NT   (Bb*Tt)   // 65536 tokens

// ---------------- scratch (device globals; no allocation allowed) ----------------
__device__ float g_x [(size_t)NT*Cc];           // residual stream (full fp32)
__device__ float g_xr[(size_t)NT*Cc];           // tf32-rounded copy of x (GEMM A input)
__device__ float g_qkv[(size_t)NT*3*Cc];        // q|k|v per token (fp32)
__device__ float g_ao[(size_t)NT*Cc];           // attention output (tf32-rounded)
__device__ float g_y[(size_t)NT*Cc];            // gemm output (pre-LN, full fp32)
__device__ float g_h[(size_t)NT*DFFd];          // MLP hidden (tf32-rounded)
__device__ float g_wpack[(size_t)Ll*Cc*3*Cc];   // packed qkv weights (tf32)
__device__ float g_wproj[(size_t)Ll*Cc*Cc];     // rounded proj weights
__device__ float g_w1r[(size_t)Ll*Cc*DFFd];     // rounded w1
__device__ float g_w2r[(size_t)Ll*DFFd*Cc];     // rounded w2

__device__ __forceinline__ float tf32r(float x) {
    float y;
    asm("cvt.rna.tf32.f32 %0, %1;" : "=f"(y) : "f"(x));
    return y;
}

__device__ __forceinline__ void cp16(void* smem, const void* gmem) {
    unsigned int s = (unsigned int)__cvta_generic_to_shared(smem);
    asm volatile("cp.async.ca.shared.global [%0], [%1], 16;\n" :: "r"(s), "l"(gmem));
}
#define CP_COMMIT() asm volatile("cp.async.commit_group;\n" ::: "memory")
#define CP_WAIT1()  asm volatile("cp.async.wait_group 1;\n" ::: "memory")

// ---------------- weight repack: wq/wk/wv (L,H,C,HS) -> (L, C, 1536), tf32-rounded
__global__ void pack_qkv_kernel(const float* __restrict__ wq,
                                const float* __restrict__ wk,
                                const float* __restrict__ wv) {
    int i = blockIdx.x * 256 + threadIdx.x;
    if (i >= Ll*Cc*3*Cc) return;
    int col = i % (3*Cc);
    int c   = (i / (3*Cc)) % Cc;
    int l   = i / (3*Cc*Cc);
    const float* src; int j;
    if (col < Cc)        { src = wq; j = col; }
    else if (col < 2*Cc) { src = wk; j = col - Cc; }
    else                 { src = wv; j = col - 2*Cc; }
    int h = j / HSs, d = j % HSs;
    g_wpack[i] = tf32r(src[(((size_t)l*Hh + h)*Cc + c)*HSs + d]);
}

// ---------------- tf32 round-copy for weights --------------------------------------
__global__ void round_copy_kernel(const float* __restrict__ src, float* __restrict__ dst, int n4) {
    int i = blockIdx.x * 256 + threadIdx.x;
    if (i >= n4) return;
    float4 v = ((const float4*)src)[i];
    v.x = tf32r(v.x); v.y = tf32r(v.y); v.z = tf32r(v.z); v.w = tf32r(v.w);
    ((float4*)dst)[i] = v;
}

// ---------------- embedding: writes fp32 x and tf32 copy ---------------------------
__global__ void embed_kernel(const int* __restrict__ idx,
                             const float* __restrict__ tok,
                             const float* __restrict__ pos) {
    int i = blockIdx.x * 256 + threadIdx.x;
    if (i >= NT*Cc/4) return;
    int c4 = i % (Cc/4);
    int token = i / (Cc/4);
    int t = token & (Tt-1);
    float4 a = ((const float4*)tok)[(size_t)idx[token]*(Cc/4) + c4];
    float4 p = ((const float4*)pos)[(size_t)t*(Cc/4) + c4];
    float4 v = make_float4(a.x+p.x, a.y+p.y, a.z+p.z, a.w+p.w);
    ((float4*)g_x)[i] = v;
    ((float4*)g_xr)[i] = make_float4(tf32r(v.x), tf32r(v.y), tf32r(v.z), tf32r(v.w));
}

// ---------------- TF32 wmma GEMM, 3-stage cp.async pipeline ------------------------
// C = A(MxK) @ B(KxN) (+bias); flags: 1=relu, 2=tf32-round output
// A,B must already be tf32-rounded. M%128==0, N%128==0, K%32==0, K>=96.
#define BM 128
#define BN 128
#define BK 32
#define APAD 36        // BK+4 floats per A row
#define BPAD 132       // BN+4 floats per B row
#define A_STG (BM*APAD)        // 4608 floats per stage
#define B_STG (BK*BPAD)        // 4224 floats per stage
#define SMEM_DYN ((3*A_STG + 3*B_STG)*4)   // 105984 bytes

__global__ void __launch_bounds__(256, 1)
gemm_tf32(const float* __restrict__ A, const float* __restrict__ B,
          const float* __restrict__ bias, float* __restrict__ Cmat,
          int M, int N, int K, int flags)
{
    extern __shared__ float dsm[];
    float* As = dsm;                 // [3][BM][APAD]
    float* Bs = dsm + 3*A_STG;       // [3][BK][BPAD]
    __shared__ float stage[8][16][16];

    int tid  = threadIdx.x;
    int warp = tid >> 5, lane = tid & 31;
    int wm = warp >> 2, wn = warp & 3;          // 2x4 warps; warp tile 64x32
    int bm = blockIdx.y * BM, bn = blockIdx.x * BN;

    wmma::fragment<wmma::accumulator,16,16,8,float> acc[4][2];
    #pragma unroll
    for (int i = 0; i < 4; i++)
        #pragma unroll
        for (int j = 0; j < 2; j++)
            wmma::fill_fragment(acc[i][j], 0.0f);

    // copy helper: stage st gets K-slice k0
    auto issue_stage = [&](int st, int k0) {
        float* as = As + st*A_STG;
        float* bs = Bs + st*B_STG;
        #pragma unroll
        for (int i = 0; i < 4; i++) {           // A: 128 rows x 8 chunks
            int idx2 = tid + 256*i;
            int row = idx2 >> 3, c4 = (idx2 & 7) * 4;
            cp16(&as[row*APAD + c4], &A[(size_t)(bm+row)*K + k0 + c4]);
        }
        #pragma unroll
        for (int i = 0; i < 4; i++) {           // B: 32 rows x 32 chunks
            int idx2 = tid + 256*i;
            int row = idx2 >> 5, c4 = (idx2 & 31) * 4;
            cp16(&bs[row*BPAD + c4], &B[(size_t)(k0+row)*N + bn + c4]);
        }
    };

    // prologue: stages 0 and 1
    issue_stage(0, 0);   CP_COMMIT();
    issue_stage(1, BK);  CP_COMMIT();

    int s = 0;
    for (int k0 = 0; k0 < K; k0 += BK) {
        CP_WAIT1();              // all groups except the newest are complete -> stage s landed
        __syncthreads();         // also orders prev-iter compute before buffer reuse below
        if (k0 + 2*BK < K) {
            int ns = s + 2; if (ns >= 3) ns -= 3;     // FIXED wrap (was broken for s==2)
            issue_stage(ns, k0 + 2*BK);
        }
        CP_COMMIT();             // exactly one group per iteration (possibly empty)

        const float* as = As + s*A_STG;
        const float* bs = Bs + s*B_STG;
        #pragma unroll
        for (int kk = 0; kk < 4; kk++) {
            wmma::fragment<wmma::matrix_a,16,16,8,wmma::precision::tf32,wmma::row_major> af[4];
            wmma::fragment<wmma::matrix_b,16,16,8,wmma::precision::tf32,wmma::row_major> bf[2];
            #pragma unroll
            for (int i = 0; i < 4; i++)
                wmma::load_matrix_sync(af[i], &as[(wm*64 + i*16)*APAD + kk*8], APAD);
            #pragma unroll
            for (int j = 0; j < 2; j++)
                wmma::load_matrix_sync(bf[j], &bs[(kk*8)*BPAD + wn*32 + j*16], BPAD);
            #pragma unroll
            for (int i = 0; i < 4; i++)
                #pragma unroll
                for (int j = 0; j < 2; j++)
                    wmma::mma_sync(acc[i][j], af[i], bf[j], acc[i][j]);
        }
        s = (s+1 == 3) ? 0 : s+1;
    }

    // epilogue: per-warp staging (static smem), float4 stores
    #pragma unroll
    for (int i = 0; i < 4; i++) {
        #pragma unroll
        for (int j = 0; j < 2; j++) {
            wmma::store_matrix_sync(&stage[warp][0][0], acc[i][j], 16, wmma::mem_row_major);
            __syncwarp();
            int grow0 = bm + wm*64 + i*16;
            int gcol0 = bn + wn*32 + j*16;
            #pragma unroll
            for (int e = 0; e < 2; e++) {
                int idx2 = e*32 + lane;
                int r = idx2 >> 2, c4 = (idx2 & 3) * 4;
                float4 v = *(float4*)&stage[warp][r][c4];
                if (bias) {
                    float4 bv = *(const float4*)&bias[gcol0 + c4];
                    v.x += bv.x; v.y += bv.y; v.z += bv.z; v.w += bv.w;
                }
                if (flags & 1) {
                    v.x = fmaxf(v.x, 0.f); v.y = fmaxf(v.y, 0.f);
                    v.z = fmaxf(v.z, 0.f); v.w = fmaxf(v.w, 0.f);
                }
                if (flags & 2) {
                    v.x = tf32r(v.x); v.y = tf32r(v.y);
                    v.z = tf32r(v.z); v.w = tf32r(v.w);
                }
                *(float4*)&Cmat[(size_t)(grow0 + r)*N + gcol0 + c4] = v;
            }
            __syncwarp();
        }
    }
}

// ---------------- attention: one warp per (b,h); T=8, HS=64; scale = C^-0.5 -------
__global__ void __launch_bounds__(128)
attn_kernel() {
    __shared__ float sq[4][8][64], sk[4][8][64], sv[4][8][64];
    __shared__ float satt[4][8][8];
    int warp = threadIdx.x >> 5, lane = threadIdx.x & 31;
    int bh = blockIdx.x * 4 + warp;
    int b = bh >> 3, h = bh & 7;
    size_t tok0 = (size_t)b * Tt;

    #pragma unroll
    for (int t = 0; t < 8; t++) {
        const float2* row2 = (const float2*)&g_qkv[(tok0 + t) * (3*Cc)];
        ((float2*)sq[warp][t])[lane] = row2[h*32 + lane];
        ((float2*)sk[warp][t])[lane] = row2[Cc/2 + h*32 + lane];
        ((float2*)sv[warp][t])[lane] = row2[Cc   + h*32 + lane];
    }
    __syncwarp();

    const float scale = 0.044194173824159216f;   // 512^-0.5
    #pragma unroll
    for (int p = lane; p < 64; p += 32) {
        int t = p >> 3, sIdx = p & 7;
        float acc = 0.f;
        #pragma unroll
        for (int d = 0; d < 64; d++) acc += sq[warp][t][d] * sk[warp][sIdx][d];
        satt[warp][t][sIdx] = (sIdx <= t) ? acc * scale : 0.0f;
    }
    __syncwarp();

    if (lane < 8) {
        int t = lane;
        float m = -1e30f;
        for (int sIdx = 0; sIdx <= t; sIdx++) m = fmaxf(m, satt[warp][t][sIdx]);
        float e[8]; float sum = 0.f;
        #pragma unroll
        for (int sIdx = 0; sIdx < 8; sIdx++) {
            e[sIdx] = (sIdx <= t) ? __expf(satt[warp][t][sIdx] - m) : 0.0f;
            sum += e[sIdx];
        }
        float inv = 1.0f / sum;
        #pragma unroll
        for (int sIdx = 0; sIdx < 8; sIdx++) satt[warp][t][sIdx] = e[sIdx] * inv;
    }
    __syncwarp();

    #pragma unroll
    for (int t = 0; t < 8; t++) {
        float a0 = 0.f, a1 = 0.f;
        #pragma unroll
        for (int sIdx = 0; sIdx < 8; sIdx++) {
            float w = satt[warp][t][sIdx];
            a0 += w * sv[warp][sIdx][lane];
            a1 += w * sv[warp][sIdx][lane + 32];
        }
        g_ao[(tok0 + t)*Cc + h*64 + lane]      = tf32r(a0);
        g_ao[(tok0 + t)*Cc + h*64 + lane + 32] = tf32r(a1);
    }
}

// ---------------- fused residual add + LayerNorm: fp32 x + tf32 copy ---------------
__global__ void __launch_bounds__(256)
add_ln_kernel(const float* __restrict__ y,
              const float* __restrict__ gamma, const float* __restrict__ beta) {
    int warp = threadIdx.x >> 5, lane = threadIdx.x & 31;
    size_t row = (size_t)blockIdx.x * 8 + warp;
    float* xr  = &g_x [row * Cc];
    float* xrr = &g_xr[row * Cc];
    const float* yr = &y[row * Cc];
    float v[16];
    float s = 0.f;
    #pragma unroll
    for (int i = 0; i < 16; i++) {
        v[i] = xr[lane + 32*i] + yr[lane + 32*i];
        s += v[i];
    }
    #pragma unroll
    for (int off = 16; off > 0; off >>= 1) s += __shfl_xor_sync(0xFFFFFFFFu, s, off);
    float mu = s * (1.0f / Cc);
    float var = 0.f;
    #pragma unroll
    for (int i = 0; i < 16; i++) { float d = v[i] - mu; var += d * d; }
    #pragma unroll
    for (int off = 16; off > 0; off >>= 1) var += __shfl_xor_sync(0xFFFFFFFFu, var, off);
    var *= (1.0f / Cc);
    float r = rsqrtf(var + 1e-5f);
    #pragma unroll
    for (int i = 0; i < 16; i++) {
        int c = lane + 32*i;
        float o = (v[i] - mu) * r * gamma[c] + beta[c];
        xr[c]  = o;
        xrr[c] = tf32r(o);
    }
}

// ---------------- logits: (NT,512) @ (512,65) + b  (full fp32) ---------------------
__global__ void __launch_bounds__(256)
logits_kernel(const float* __restrict__ lmw, const float* __restrict__ lmb,
              float* __restrict__ out) {
    __shared__ float As2[16][512];
    size_t row0 = (size_t)blockIdx.x * 16;
    for (int i = threadIdx.x; i < 16*512; i += 256)
        As2[i >> 9][i & 511] = g_x[(row0 + (i >> 9))*Cc + (i & 511)];
    __syncthreads();
    for (int idx2 = threadIdx.x; idx2 < 16*Vv; idx2 += 256) {
        int r = idx2 / Vv, c = idx2 % Vv;
        float s = lmb[c];
        #pragma unroll 8
        for (int k = 0; k < 512; k++) s += As2[r][k] * lmw[k*Vv + c];
        out[(row0 + r)*Vv + c] = s;
    }
}

// ---------------- host launch ------------------------------------------------------
extern "C" void kernel_launch(void* const* d_in, const int* in_sizes, int n_in,
                              void* d_out, int out_size) {
    const int*   idx    = (const int*)  d_in[0];
    const float* tok    = (const float*)d_in[1];
    const float* pos    = (const float*)d_in[2];
    const float* wq     = (const float*)d_in[3];
    const float* wk     = (const float*)d_in[4];
    const float* wv     = (const float*)d_in[5];
    const float* proj_w = (const float*)d_in[6];
    const float* proj_b = (const float*)d_in[7];
    const float* w1     = (const float*)d_in[8];
    const float* b1     = (const float*)d_in[9];
    const float* w2     = (const float*)d_in[10];
    const float* b2     = (const float*)d_in[11];
    const float* ln1g   = (const float*)d_in[12];
    const float* ln1b   = (const float*)d_in[13];
    const float* ln2g   = (const float*)d_in[14];
    const float* ln2b   = (const float*)d_in[15];
    const float* lm_w   = (const float*)d_in[16];
    const float* lm_b   = (const float*)d_in[17];
    float* out = (float*)d_out;

    cudaFuncSetAttribute(gemm_tf32, cudaFuncAttributeMaxDynamicSharedMemorySize, SMEM_DYN);

    float *x, *xr, *qkv, *ao, *y, *hbuf, *wp, *wpr, *w1r, *w2r;
    cudaGetSymbolAddress((void**)&x,    g_x);
    cudaGetSymbolAddress((void**)&xr,   g_xr);
    cudaGetSymbolAddress((void**)&qkv,  g_qkv);
    cudaGetSymbolAddress((void**)&ao,   g_ao);
    cudaGetSymbolAddress((void**)&y,    g_y);
    cudaGetSymbolAddress((void**)&hbuf, g_h);
    cudaGetSymbolAddress((void**)&wp,   g_wpack);
    cudaGetSymbolAddress((void**)&wpr,  g_wproj);
    cudaGetSymbolAddress((void**)&w1r,  g_w1r);
    cudaGetSymbolAddress((void**)&w2r,  g_w2r);

    int nPack = Ll*Cc*3*Cc;
    pack_qkv_kernel<<<(nPack + 255)/256, 256>>>(wq, wk, wv);
    round_copy_kernel<<<(Ll*Cc*Cc/4 + 255)/256, 256>>>(proj_w, wpr, Ll*Cc*Cc/4);
    round_copy_kernel<<<(Ll*Cc*DFFd/4 + 255)/256, 256>>>(w1, w1r, Ll*Cc*DFFd/4);
    round_copy_kernel<<<(Ll*DFFd*Cc/4 + 255)/256, 256>>>(w2, w2r, Ll*DFFd*Cc/4);
    embed_kernel<<<(NT*Cc/4 + 255)/256, 256>>>(idx, tok, pos);

    for (int l = 0; l < Ll; l++) {
        // QKV: (NT,512) @ (512,1536)
        gemm_tf32<<<dim3(3*Cc/BN, NT/BM), 256, SMEM_DYN>>>(
            xr, wp + (size_t)l*Cc*3*Cc, nullptr, qkv, NT, 3*Cc, Cc, 0);
        // attention
        attn_kernel<<<Bb*Hh/4, 128>>>();
        // proj: (NT,512) @ (512,512) + b
        gemm_tf32<<<dim3(Cc/BN, NT/BM), 256, SMEM_DYN>>>(
            ao, wpr + (size_t)l*Cc*Cc, proj_b + (size_t)l*Cc, y, NT, Cc, Cc, 0);
        // x = LN(x + y)
        add_ln_kernel<<<NT/8, 256>>>(y, ln1g + (size_t)l*Cc, ln1b + (size_t)l*Cc);
        // MLP up: (NT,512) @ (512,2048) + b, relu, tf32 out
        gemm_tf32<<<dim3(DFFd/BN, NT/BM), 256, SMEM_DYN>>>(
            xr, w1r + (size_t)l*Cc*DFFd, b1 + (size_t)l*DFFd, hbuf, NT, DFFd, Cc, 3);
        // MLP down: (NT,2048) @ (2048,512) + b
        gemm_tf32<<<dim3(Cc/BN, NT/BM), 256, SMEM_DYN>>>(
            hbuf, w2r + (size_t)l*DFFd*Cc, b2 + (size_t)l*Cc, y, NT, Cc, DFFd, 0);
        // x = LN(x + y)
        add_ln_kernel<<<NT/8, 256>>>(y, ln2g + (size_t)l*Cc, ln2b + (size_t)l*Cc);
    }

    logits_kernel<<<NT/16, 256>>>(lm_w, lm_b, out);
}

// round 8
// speedup vs baseline: 3.1228x; 3.1228x over previous
#include <cuda_runtime.h>
#include <cuda_fp16.h>
#include <mma.h>
#include <math.h>
#include <cstdint>
#include <stdint.h>

using namespace nvcuda;

// Problem dims
#define Bb   8192
#define Tt   8
#define Vv   65
#define Cc   512
#define Hh   8
#define HSs  64
#define Ll   6
#define DFFd 2048
#define NT   (Bb*Tt)   // 65536 tokens

// ---------------- scratch (device globals) ----------------
__device__ float  g_x  [(size_t)NT*Cc];          // residual stream (fp32)
__device__ __half g_xh [(size_t)NT*Cc];          // half copy of x (GEMM A)
__device__ float  g_qkv[(size_t)NT*3*Cc];        // q|k|v (fp32)
__device__ __half g_aoh[(size_t)NT*Cc];          // attention out (half)
__device__ float  g_y  [(size_t)NT*Cc];          // pre-LN gemm out (fp32)
__device__ __half g_hh [(size_t)NT*DFFd];        // MLP hidden (half)
__device__ __half g_wqkvh[(size_t)Ll*Cc*3*Cc];   // qkv weights (C,1536) K-major
__device__ __half g_wprojh[(size_t)Ll*Cc*Cc];    // proj (C,C)
__device__ __half g_w1h[(size_t)Ll*Cc*DFFd];     // w1 (C,DFF)
__device__ __half g_w2h[(size_t)Ll*DFFd*Cc];     // w2 (DFF,C)

__device__ __forceinline__ void cp16(void* smem, const void* gmem) {
    unsigned int s = (unsigned int)__cvta_generic_to_shared(smem);
    asm volatile("cp.async.ca.shared.global [%0], [%1], 16;\n" :: "r"(s), "l"(gmem));
}
#define CP_COMMIT() asm volatile("cp.async.commit_group;\n" ::: "memory")
#define CP_WAIT1()  asm volatile("cp.async.wait_group 1;\n" ::: "memory")

// ---------------- weight prep ------------------------------------------------------
// wq/wk/wv (L,H,C,HS) -> (L, C, 1536) row-major half
__global__ void pack_qkv_h(const float* __restrict__ wq,
                           const float* __restrict__ wk,
                           const float* __restrict__ wv) {
    int i = blockIdx.x * 256 + threadIdx.x;
    if (i >= Ll*Cc*3*Cc) return;
    int col = i % (3*Cc);
    int c   = (i / (3*Cc)) % Cc;
    int l   = i / (3*Cc*Cc);
    const float* src; int j;
    if (col < Cc)        { src = wq; j = col; }
    else if (col < 2*Cc) { src = wk; j = col - Cc; }
    else                 { src = wv; j = col - 2*Cc; }
    int h = j / HSs, d = j % HSs;
    g_wqkvh[i] = __float2half_rn(src[(((size_t)l*Hh + h)*Cc + c)*HSs + d]);
}

__global__ void half_copy(const float* __restrict__ src, __half* __restrict__ dst, int n) {
    int i = blockIdx.x * 256 + threadIdx.x;
    if (i >= n) return;
    dst[i] = __float2half_rn(src[i]);
}

// ---------------- embedding: fp32 x + half copy ------------------------------------
__global__ void embed_kernel(const int* __restrict__ idx,
                             const float* __restrict__ tok,
                             const float* __restrict__ pos) {
    int i = blockIdx.x * 256 + threadIdx.x;
    if (i >= NT*Cc/4) return;
    int c4 = i % (Cc/4);
    int token = i / (Cc/4);
    int t = token & (Tt-1);
    float4 a = ((const float4*)tok)[(size_t)idx[token]*(Cc/4) + c4];
    float4 p = ((const float4*)pos)[(size_t)t*(Cc/4) + c4];
    float4 v = make_float4(a.x+p.x, a.y+p.y, a.z+p.z, a.w+p.w);
    ((float4*)g_x)[i] = v;
    __half2 h0 = __floats2half2_rn(v.x, v.y);
    __half2 h1 = __floats2half2_rn(v.z, v.w);
    ((__half2*)g_xh)[i*2]   = h0;
    ((__half2*)g_xh)[i*2+1] = h1;
}

// ---------------- FP16 wmma GEMM, 2-stage cp.async ---------------------------------
// Cf/Ch(M,N) = A(M,K)h @ B(K,N)h (+bias); relu optional. Either output may be null.
// M%128==0, N%256==0, K%32==0.
#define BM 128
#define BN 256
#define BK 32
#define APADH 40       // halves per A row (32+8)
#define BPADH 272      // halves per B row (256+16)
#define A_STGH (BM*APADH)      // 5120 halves
#define B_STGH (BK*BPADH)      // 8704 halves
#define SMEM_DYN ((2*A_STGH + 2*B_STGH)*2)   // 55296 bytes

__global__ void __launch_bounds__(256)
gemm_h(const __half* __restrict__ A, const __half* __restrict__ B,
       const float* __restrict__ bias,
       float* __restrict__ Cf, __half* __restrict__ Ch,
       int M, int N, int K, int relu)
{
    extern __shared__ __half hsm[];
    __half* As = hsm;                 // [2][BM][APADH]
    __half* Bs = hsm + 2*A_STGH;      // [2][BK][BPADH]
    __shared__ float stage[8][16][16];

    int tid  = threadIdx.x;
    int warp = tid >> 5, lane = tid & 31;
    int wm = warp >> 2, wn = warp & 3;          // 2x4 warps; warp tile 64x64
    int bm = blockIdx.y * BM, bn = blockIdx.x * BN;

    wmma::fragment<wmma::accumulator,16,16,16,float> acc[4][4];
    #pragma unroll
    for (int i = 0; i < 4; i++)
        #pragma unroll
        for (int j = 0; j < 4; j++)
            wmma::fill_fragment(acc[i][j], 0.0f);

    // A: 128 rows x 4 chunks(8 halves) = 512 chunks; B: 32 rows x 32 chunks = 1024
    auto issue_stage = [&](int st, int k0) {
        __half* as = As + st*A_STGH;
        __half* bs = Bs + st*B_STGH;
        #pragma unroll
        for (int i = 0; i < 2; i++) {
            int idx2 = tid + 256*i;
            int row = idx2 >> 2, c8 = (idx2 & 3) * 8;
            cp16(&as[row*APADH + c8], &A[(size_t)(bm+row)*K + k0 + c8]);
        }
        #pragma unroll
        for (int i = 0; i < 4; i++) {
            int idx2 = tid + 256*i;
            int row = idx2 >> 5, c8 = (idx2 & 31) * 8;
            cp16(&bs[row*BPADH + c8], &B[(size_t)(k0+row)*N + bn + c8]);
        }
    };

    issue_stage(0, 0);
    CP_COMMIT();

    int s = 0;
    for (int k0 = 0; k0 < K; k0 += BK, s ^= 1) {
        if (k0 + BK < K) issue_stage(s^1, k0 + BK);
        CP_COMMIT();
        CP_WAIT1();
        __syncthreads();

        const __half* as = As + s*A_STGH;
        const __half* bs = Bs + s*B_STGH;
        #pragma unroll
        for (int kk = 0; kk < 2; kk++) {
            wmma::fragment<wmma::matrix_a,16,16,16,__half,wmma::row_major> af[4];
            wmma::fragment<wmma::matrix_b,16,16,16,__half,wmma::row_major> bf[4];
            #pragma unroll
            for (int i = 0; i < 4; i++)
                wmma::load_matrix_sync(af[i], &as[(wm*64 + i*16)*APADH + kk*16], APADH);
            #pragma unroll
            for (int j = 0; j < 4; j++)
                wmma::load_matrix_sync(bf[j], &bs[(kk*16)*BPADH + wn*64 + j*16], BPADH);
            #pragma unroll
            for (int i = 0; i < 4; i++)
                #pragma unroll
                for (int j = 0; j < 4; j++)
                    wmma::mma_sync(acc[i][j], af[i], bf[j], acc[i][j]);
        }
        __syncthreads();
    }

    // epilogue
    #pragma unroll
    for (int i = 0; i < 4; i++) {
        #pragma unroll
        for (int j = 0; j < 4; j++) {
            wmma::store_matrix_sync(&stage[warp][0][0], acc[i][j], 16, wmma::mem_row_major);
            __syncwarp();
            int grow0 = bm + wm*64 + i*16;
            int gcol0 = bn + wn*64 + j*16;
            #pragma unroll
            for (int e = 0; e < 2; e++) {
                int idx2 = e*32 + lane;
                int r = idx2 >> 2, c4 = (idx2 & 3) * 4;
                float4 v = *(float4*)&stage[warp][r][c4];
                if (bias) {
                    float4 bv = *(const float4*)&bias[gcol0 + c4];
                    v.x += bv.x; v.y += bv.y; v.z += bv.z; v.w += bv.w;
                }
                if (relu) {
                    v.x = fmaxf(v.x, 0.f); v.y = fmaxf(v.y, 0.f);
                    v.z = fmaxf(v.z, 0.f); v.w = fmaxf(v.w, 0.f);
                }
                size_t off = (size_t)(grow0 + r)*N + gcol0 + c4;
                if (Cf) *(float4*)&Cf[off] = v;
                if (Ch) {
                    __half2 p0 = __floats2half2_rn(v.x, v.y);
                    __half2 p1 = __floats2half2_rn(v.z, v.w);
                    *(__half2*)&Ch[off]     = p0;
                    *(__half2*)&Ch[off + 2] = p1;
                }
            }
            __syncwarp();
        }
    }
}

// ---------------- attention: one warp per (b,h); T=8, HS=64; scale = C^-0.5 -------
__global__ void __launch_bounds__(128)
attn_kernel() {
    __shared__ float sq[4][8][64], sk[4][8][64], sv[4][8][64];
    __shared__ float satt[4][8][8];
    int warp = threadIdx.x >> 5, lane = threadIdx.x & 31;
    int bh = blockIdx.x * 4 + warp;
    int b = bh >> 3, h = bh & 7;
    size_t tok0 = (size_t)b * Tt;

    #pragma unroll
    for (int t = 0; t < 8; t++) {
        const float2* row2 = (const float2*)&g_qkv[(tok0 + t) * (3*Cc)];
        ((float2*)sq[warp][t])[lane] = row2[h*32 + lane];
        ((float2*)sk[warp][t])[lane] = row2[Cc/2 + h*32 + lane];
        ((float2*)sv[warp][t])[lane] = row2[Cc   + h*32 + lane];
    }
    __syncwarp();

    const float scale = 0.044194173824159216f;   // 512^-0.5
    #pragma unroll
    for (int p = lane; p < 64; p += 32) {
        int t = p >> 3, sIdx = p & 7;
        float acc = 0.f;
        #pragma unroll
        for (int d = 0; d < 64; d++) acc += sq[warp][t][d] * sk[warp][sIdx][d];
        satt[warp][t][sIdx] = (sIdx <= t) ? acc * scale : 0.0f;
    }
    __syncwarp();

    if (lane < 8) {
        int t = lane;
        float m = -1e30f;
        for (int sIdx = 0; sIdx <= t; sIdx++) m = fmaxf(m, satt[warp][t][sIdx]);
        float e[8]; float sum = 0.f;
        #pragma unroll
        for (int sIdx = 0; sIdx < 8; sIdx++) {
            e[sIdx] = (sIdx <= t) ? __expf(satt[warp][t][sIdx] - m) : 0.0f;
            sum += e[sIdx];
        }
        float inv = 1.0f / sum;
        #pragma unroll
        for (int sIdx = 0; sIdx < 8; sIdx++) satt[warp][t][sIdx] = e[sIdx] * inv;
    }
    __syncwarp();

    #pragma unroll
    for (int t = 0; t < 8; t++) {
        float a0 = 0.f, a1 = 0.f;
        #pragma unroll
        for (int sIdx = 0; sIdx < 8; sIdx++) {
            float w = satt[warp][t][sIdx];
            a0 += w * sv[warp][sIdx][lane];
            a1 += w * sv[warp][sIdx][lane + 32];
        }
        g_aoh[(tok0 + t)*Cc + h*64 + lane]      = __float2half_rn(a0);
        g_aoh[(tok0 + t)*Cc + h*64 + lane + 32] = __float2half_rn(a1);
    }
}

// ---------------- fused residual add + LayerNorm: fp32 x + half copy ---------------
__global__ void __launch_bounds__(256)
add_ln_kernel(const float* __restrict__ y,
              const float* __restrict__ gamma, const float* __restrict__ beta) {
    int warp = threadIdx.x >> 5, lane = threadIdx.x & 31;
    size_t row = (size_t)blockIdx.x * 8 + warp;
    float*  xr = &g_x [row * Cc];
    __half* xh = &g_xh[row * Cc];
    const float* yr = &y[row * Cc];
    float v[16];
    float s = 0.f;
    #pragma unroll
    for (int i = 0; i < 16; i++) {
        v[i] = xr[lane + 32*i] + yr[lane + 32*i];
        s += v[i];
    }
    #pragma unroll
    for (int off = 16; off > 0; off >>= 1) s += __shfl_xor_sync(0xFFFFFFFFu, s, off);
    float mu = s * (1.0f / Cc);
    float var = 0.f;
    #pragma unroll
    for (int i = 0; i < 16; i++) { float d = v[i] - mu; var += d * d; }
    #pragma unroll
    for (int off = 16; off > 0; off >>= 1) var += __shfl_xor_sync(0xFFFFFFFFu, var, off);
    var *= (1.0f / Cc);
    float r = rsqrtf(var + 1e-5f);
    #pragma unroll
    for (int i = 0; i < 16; i++) {
        int c = lane + 32*i;
        float o = (v[i] - mu) * r * gamma[c] + beta[c];
        xr[c] = o;
        xh[c] = __float2half_rn(o);
    }
}

// ---------------- logits: (NT,512) @ (512,65) + b  (full fp32) ---------------------
__global__ void __launch_bounds__(256)
logits_kernel(const float* __restrict__ lmw, const float* __restrict__ lmb,
              float* __restrict__ out) {
    __shared__ float As2[16][512];
    size_t row0 = (size_t)blockIdx.x * 16;
    for (int i = threadIdx.x; i < 16*512; i += 256)
        As2[i >> 9][i & 511] = g_x[(row0 + (i >> 9))*Cc + (i & 511)];
    __syncthreads();
    for (int idx2 = threadIdx.x; idx2 < 16*Vv; idx2 += 256) {
        int r = idx2 / Vv, c = idx2 % Vv;
        float s = lmb[c];
        #pragma unroll 8
        for (int k = 0; k < 512; k++) s += As2[r][k] * lmw[k*Vv + c];
        out[(row0 + r)*Vv + c] = s;
    }
}

// ---------------- host launch ------------------------------------------------------
extern "C" void kernel_launch(void* const* d_in, const int* in_sizes, int n_in,
                              void* d_out, int out_size) {
    const int*   idx    = (const int*)  d_in[0];
    const float* tok    = (const float*)d_in[1];
    const float* pos    = (const float*)d_in[2];
    const float* wq     = (const float*)d_in[3];
    const float* wk     = (const float*)d_in[4];
    const float* wv     = (const float*)d_in[5];
    const float* proj_w = (const float*)d_in[6];
    const float* proj_b = (const float*)d_in[7];
    const float* w1     = (const float*)d_in[8];
    const float* b1     = (const float*)d_in[9];
    const float* w2     = (const float*)d_in[10];
    const float* b2     = (const float*)d_in[11];
    const float* ln1g   = (const float*)d_in[12];
    const float* ln1b   = (const float*)d_in[13];
    const float* ln2g   = (const float*)d_in[14];
    const float* ln2b   = (const float*)d_in[15];
    const float* lm_w   = (const float*)d_in[16];
    const float* lm_b   = (const float*)d_in[17];
    float* out = (float*)d_out;

    cudaFuncSetAttribute(gemm_h, cudaFuncAttributeMaxDynamicSharedMemorySize, SMEM_DYN);

    float *x, *y, *qkv;
    __half *xh, *aoh, *hh, *wqkvh, *wprojh, *w1h, *w2h;
    cudaGetSymbolAddress((void**)&x,     g_x);
    cudaGetSymbolAddress((void**)&xh,    g_xh);
    cudaGetSymbolAddress((void**)&qkv,   g_qkv);
    cudaGetSymbolAddress((void**)&aoh,   g_aoh);
    cudaGetSymbolAddress((void**)&y,     g_y);
    cudaGetSymbolAddress((void**)&hh,    g_hh);
    cudaGetSymbolAddress((void**)&wqkvh, g_wqkvh);
    cudaGetSymbolAddress((void**)&wprojh,g_wprojh);
    cudaGetSymbolAddress((void**)&w1h,   g_w1h);
    cudaGetSymbolAddress((void**)&w2h,   g_w2h);

    pack_qkv_h<<<(Ll*Cc*3*Cc + 255)/256, 256>>>(wq, wk, wv);
    half_copy<<<(Ll*Cc*Cc + 255)/256, 256>>>(proj_w, wprojh, Ll*Cc*Cc);
    half_copy<<<(Ll*Cc*DFFd + 255)/256, 256>>>(w1, w1h, Ll*Cc*DFFd);
    half_copy<<<(Ll*DFFd*Cc + 255)/256, 256>>>(w2, w2h, Ll*DFFd*Cc);
    embed_kernel<<<(NT*Cc/4 + 255)/256, 256>>>(idx, tok, pos);

    for (int l = 0; l < Ll; l++) {
        // QKV: (NT,512)h @ (512,1536)h -> fp32
        gemm_h<<<dim3(3*Cc/BN, NT/BM), 256, SMEM_DYN>>>(
            xh, wqkvh + (size_t)l*Cc*3*Cc, nullptr, qkv, nullptr, NT, 3*Cc, Cc, 0);
        // attention -> half ao
        attn_kernel<<<Bb*Hh/4, 128>>>();
        // proj: (NT,512)h @ (512,512)h + b -> fp32 y
        gemm_h<<<dim3(Cc/BN, NT/BM), 256, SMEM_DYN>>>(
            aoh, wprojh + (size_t)l*Cc*Cc, proj_b + (size_t)l*Cc, y, nullptr, NT, Cc, Cc, 0);
        // x = LN(x + y); writes fp32 + half
        add_ln_kernel<<<NT/8, 256>>>(y, ln1g + (size_t)l*Cc, ln1b + (size_t)l*Cc);
        // MLP up: (NT,512)h @ (512,2048)h + b, relu -> half h
        gemm_h<<<dim3(DFFd/BN, NT/BM), 256, SMEM_DYN>>>(
            xh, w1h + (size_t)l*Cc*DFFd, b1 + (size_t)l*DFFd, nullptr, hh, NT, DFFd, Cc, 1);
        // MLP down: (NT,2048)h @ (2048,512)h + b -> fp32 y
        gemm_h<<<dim3(Cc/BN, NT/BM), 256, SMEM_DYN>>>(
            hh, w2h + (size_t)l*DFFd*Cc, b2 + (size_t)l*Cc, y, nullptr, NT, Cc, DFFd, 0);
        // x = LN(x + y)
        add_ln_kernel<<<NT/8, 256>>>(y, ln2g + (size_t)l*Cc, ln2b + (size_t)l*Cc);
    }

    logits_kernel<<<NT/16, 256>>>(lm_w, lm_b, out);
}

// round 9
// speedup vs baseline: 3.4345x; 1.0998x over previous
#include <cuda_runtime.h>
#include <cuda_fp16.h>
#include <mma.h>
#include <math.h>
#include <cstdint>
#include <stdint.h>

using namespace nvcuda;

// Problem dims
#define Bb   8192
#define Tt   8
#define Vv   65
#define Cc   512
#define Hh   8
#define HSs  64
#define Ll   6
#define DFFd 2048
#define NT   (Bb*Tt)   // 65536 tokens

// ---------------- scratch (device globals) ----------------
__device__ float  g_x  [(size_t)NT*Cc];          // residual stream (fp32)
__device__ __half g_xh [(size_t)NT*Cc];          // half copy of x (GEMM A)
__device__ __half g_qkvh[(size_t)NT*3*Cc];       // q|k|v (half)
__device__ __half g_aoh[(size_t)NT*Cc];          // attention out (half)
__device__ float  g_y  [(size_t)NT*Cc];          // pre-LN gemm out (fp32)
__device__ __half g_hh [(size_t)NT*DFFd];        // MLP hidden (half)
__device__ __half g_wqkvh[(size_t)Ll*Cc*3*Cc];   // qkv weights (C,1536)
__device__ __half g_wprojh[(size_t)Ll*Cc*Cc];    // proj (C,C)
__device__ __half g_w1h[(size_t)Ll*Cc*DFFd];     // w1 (C,DFF)
__device__ __half g_w2h[(size_t)Ll*DFFd*Cc];     // w2 (DFF,C)

__device__ __forceinline__ void cp16(void* smem, const void* gmem) {
    unsigned int s = (unsigned int)__cvta_generic_to_shared(smem);
    asm volatile("cp.async.ca.shared.global [%0], [%1], 16;\n" :: "r"(s), "l"(gmem));
}
#define CP_COMMIT() asm volatile("cp.async.commit_group;\n" ::: "memory")
#define CP_WAIT1()  asm volatile("cp.async.wait_group 1;\n" ::: "memory")

// ---------------- weight prep ------------------------------------------------------
__global__ void pack_qkv_h(const float* __restrict__ wq,
                           const float* __restrict__ wk,
                           const float* __restrict__ wv) {
    int i = blockIdx.x * 256 + threadIdx.x;
    if (i >= Ll*Cc*3*Cc) return;
    int col = i % (3*Cc);
    int c   = (i / (3*Cc)) % Cc;
    int l   = i / (3*Cc*Cc);
    const float* src; int j;
    if (col < Cc)        { src = wq; j = col; }
    else if (col < 2*Cc) { src = wk; j = col - Cc; }
    else                 { src = wv; j = col - 2*Cc; }
    int h = j / HSs, d = j % HSs;
    g_wqkvh[i] = __float2half_rn(src[(((size_t)l*Hh + h)*Cc + c)*HSs + d]);
}

__global__ void half_copy(const float* __restrict__ src, __half* __restrict__ dst, int n2) {
    int i = blockIdx.x * 256 + threadIdx.x;
    if (i >= n2) return;
    float2 v = ((const float2*)src)[i];
    ((__half2*)dst)[i] = __floats2half2_rn(v.x, v.y);
}

// ---------------- embedding: fp32 x + half copy ------------------------------------
__global__ void embed_kernel(const int* __restrict__ idx,
                             const float* __restrict__ tok,
                             const float* __restrict__ pos) {
    int i = blockIdx.x * 256 + threadIdx.x;
    if (i >= NT*Cc/4) return;
    int c4 = i % (Cc/4);
    int token = i / (Cc/4);
    int t = token & (Tt-1);
    float4 a = ((const float4*)tok)[(size_t)idx[token]*(Cc/4) + c4];
    float4 p = ((const float4*)pos)[(size_t)t*(Cc/4) + c4];
    float4 v = make_float4(a.x+p.x, a.y+p.y, a.z+p.z, a.w+p.w);
    ((float4*)g_x)[i] = v;
    ((__half2*)g_xh)[i*2]   = __floats2half2_rn(v.x, v.y);
    ((__half2*)g_xh)[i*2+1] = __floats2half2_rn(v.z, v.w);
}

// ---------------- FP16 wmma GEMM, 3-stage cp.async, 1 bar/iter ---------------------
// Cf/Ch(M,N) = A(M,K)h @ B(K,N)h (+bias); relu optional. Either output may be null.
// M%128==0, N%256==0, K%32==0, K>=96.
#define BM 128
#define BN 256
#define BK 32
#define APADH 40       // halves per A row
#define BPADH 272      // halves per B row
#define A_STGH (BM*APADH)      // 5120 halves
#define B_STGH (BK*BPADH)      // 8704 halves
#define SMEM_DYN (3*(A_STGH + B_STGH)*2)   // 82944 bytes

__global__ void __launch_bounds__(256)
gemm_h(const __half* __restrict__ A, const __half* __restrict__ B,
       const float* __restrict__ bias,
       float* __restrict__ Cf, __half* __restrict__ Ch,
       int M, int N, int K, int relu)
{
    extern __shared__ __half hsm[];
    __half* As = hsm;                 // [3][BM][APADH]
    __half* Bs = hsm + 3*A_STGH;      // [3][BK][BPADH]
    __shared__ float stage[8][16][16];

    int tid  = threadIdx.x;
    int warp = tid >> 5, lane = tid & 31;
    int wm = warp >> 2, wn = warp & 3;          // 2x4 warps; warp tile 64x64
    int bm = blockIdx.y * BM, bn = blockIdx.x * BN;
    int nt = K / BK;

    wmma::fragment<wmma::accumulator,16,16,16,float> acc[4][4];
    #pragma unroll
    for (int i = 0; i < 4; i++)
        #pragma unroll
        for (int j = 0; j < 4; j++)
            wmma::fill_fragment(acc[i][j], 0.0f);

    auto issue_stage = [&](int st, int k0) {
        __half* as = As + st*A_STGH;
        __half* bs = Bs + st*B_STGH;
        #pragma unroll
        for (int i = 0; i < 2; i++) {
            int idx2 = tid + 256*i;
            int row = idx2 >> 2, c8 = (idx2 & 3) * 8;
            cp16(&as[row*APADH + c8], &A[(size_t)(bm+row)*K + k0 + c8]);
        }
        #pragma unroll
        for (int i = 0; i < 4; i++) {
            int idx2 = tid + 256*i;
            int row = idx2 >> 5, c8 = (idx2 & 31) * 8;
            cp16(&bs[row*BPADH + c8], &B[(size_t)(k0+row)*N + bn + c8]);
        }
    };

    issue_stage(0, 0);  CP_COMMIT();
    issue_stage(1, BK); CP_COMMIT();

    for (int i = 0; i < nt; i++) {
        int s = i % 3;
        CP_WAIT1();              // stage i landed
        __syncthreads();         // all warps done computing stage i-1 -> buffer (i+2)%3 free
        if (i + 2 < nt) {
            int ns = i + 2; ns -= (ns / 3) * 3;
            issue_stage(ns, (i + 2) * BK);
        }
        CP_COMMIT();             // exactly one group per iter

        const __half* as = As + s*A_STGH;
        const __half* bs = Bs + s*B_STGH;
        #pragma unroll
        for (int kk = 0; kk < 2; kk++) {
            wmma::fragment<wmma::matrix_a,16,16,16,__half,wmma::row_major> af[4];
            wmma::fragment<wmma::matrix_b,16,16,16,__half,wmma::row_major> bf[4];
            #pragma unroll
            for (int i2 = 0; i2 < 4; i2++)
                wmma::load_matrix_sync(af[i2], &as[(wm*64 + i2*16)*APADH + kk*16], APADH);
            #pragma unroll
            for (int j = 0; j < 4; j++)
                wmma::load_matrix_sync(bf[j], &bs[(kk*16)*BPADH + wn*64 + j*16], BPADH);
            #pragma unroll
            for (int i2 = 0; i2 < 4; i2++)
                #pragma unroll
                for (int j = 0; j < 4; j++)
                    wmma::mma_sync(acc[i2][j], af[i2], bf[j], acc[i2][j]);
        }
    }
    __syncthreads();

    // epilogue
    #pragma unroll
    for (int i = 0; i < 4; i++) {
        #pragma unroll
        for (int j = 0; j < 4; j++) {
            wmma::store_matrix_sync(&stage[warp][0][0], acc[i][j], 16, wmma::mem_row_major);
            __syncwarp();
            int grow0 = bm + wm*64 + i*16;
            int gcol0 = bn + wn*64 + j*16;
            #pragma unroll
            for (int e = 0; e < 2; e++) {
                int idx2 = e*32 + lane;
                int r = idx2 >> 2, c4 = (idx2 & 3) * 4;
                float4 v = *(float4*)&stage[warp][r][c4];
                if (bias) {
                    float4 bv = *(const float4*)&bias[gcol0 + c4];
                    v.x += bv.x; v.y += bv.y; v.z += bv.z; v.w += bv.w;
                }
                if (relu) {
                    v.x = fmaxf(v.x, 0.f); v.y = fmaxf(v.y, 0.f);
                    v.z = fmaxf(v.z, 0.f); v.w = fmaxf(v.w, 0.f);
                }
                size_t off = (size_t)(grow0 + r)*N + gcol0 + c4;
                if (Cf) *(float4*)&Cf[off] = v;
                if (Ch) {
                    *(__half2*)&Ch[off]     = __floats2half2_rn(v.x, v.y);
                    *(__half2*)&Ch[off + 2] = __floats2half2_rn(v.z, v.w);
                }
            }
            __syncwarp();
        }
    }
}

// ---------------- attention: one warp per (b,h); T=8, HS=64; scale = C^-0.5 -------
// qkv in half; smem rows padded to 66 floats (kills 8-way bank conflicts in QK loop)
__global__ void __launch_bounds__(128)
attn_kernel() {
    __shared__ float sq[4][8][66], sk[4][8][66], sv[4][8][66];
    __shared__ float satt[4][8][9];
    int warp = threadIdx.x >> 5, lane = threadIdx.x & 31;
    int bh = blockIdx.x * 4 + warp;
    int b = bh >> 3, h = bh & 7;
    size_t tok0 = (size_t)b * Tt;

    #pragma unroll
    for (int t = 0; t < 8; t++) {
        const __half2* row2 = (const __half2*)&g_qkvh[(tok0 + t) * (3*Cc)];
        float2 qf = __half22float2(row2[          h*32 + lane]);
        float2 kf = __half22float2(row2[Cc/2    + h*32 + lane]);
        float2 vf = __half22float2(row2[Cc      + h*32 + lane]);
        sq[warp][t][2*lane] = qf.x; sq[warp][t][2*lane+1] = qf.y;
        sk[warp][t][2*lane] = kf.x; sk[warp][t][2*lane+1] = kf.y;
        sv[warp][t][2*lane] = vf.x; sv[warp][t][2*lane+1] = vf.y;
    }
    __syncwarp();

    const float scale = 0.044194173824159216f;   // 512^-0.5
    #pragma unroll
    for (int p = lane; p < 64; p += 32) {
        int t = p >> 3, sIdx = p & 7;
        float acc = 0.f;
        #pragma unroll
        for (int d = 0; d < 64; d++) acc += sq[warp][t][d] * sk[warp][sIdx][d];
        satt[warp][t][sIdx] = (sIdx <= t) ? acc * scale : 0.0f;
    }
    __syncwarp();

    if (lane < 8) {
        int t = lane;
        float m = -1e30f;
        for (int sIdx = 0; sIdx <= t; sIdx++) m = fmaxf(m, satt[warp][t][sIdx]);
        float e[8]; float sum = 0.f;
        #pragma unroll
        for (int sIdx = 0; sIdx < 8; sIdx++) {
            e[sIdx] = (sIdx <= t) ? __expf(satt[warp][t][sIdx] - m) : 0.0f;
            sum += e[sIdx];
        }
        float inv = 1.0f / sum;
        #pragma unroll
        for (int sIdx = 0; sIdx < 8; sIdx++) satt[warp][t][sIdx] = e[sIdx] * inv;
    }
    __syncwarp();

    #pragma unroll
    for (int t = 0; t < 8; t++) {
        float a0 = 0.f, a1 = 0.f;
        #pragma unroll
        for (int sIdx = 0; sIdx < 8; sIdx++) {
            float w = satt[warp][t][sIdx];
            a0 += w * sv[warp][sIdx][lane];
            a1 += w * sv[warp][sIdx][lane + 32];
        }
        g_aoh[(tok0 + t)*Cc + h*64 + lane]      = __float2half_rn(a0);
        g_aoh[(tok0 + t)*Cc + h*64 + lane + 32] = __float2half_rn(a1);
    }
}

// ---------------- fused residual add + LayerNorm: fp32 x + half copy ---------------
__global__ void __launch_bounds__(256)
add_ln_kernel(const float* __restrict__ y,
              const float* __restrict__ gamma, const float* __restrict__ beta) {
    int warp = threadIdx.x >> 5, lane = threadIdx.x & 31;
    size_t row = (size_t)blockIdx.x * 8 + warp;
    float*  xr = &g_x [row * Cc];
    __half* xh = &g_xh[row * Cc];
    const float* yr = &y[row * Cc];
    float v[16];
    float s = 0.f;
    #pragma unroll
    for (int i = 0; i < 16; i++) {
        v[i] = xr[lane + 32*i] + yr[lane + 32*i];
        s += v[i];
    }
    #pragma unroll
    for (int off = 16; off > 0; off >>= 1) s += __shfl_xor_sync(0xFFFFFFFFu, s, off);
    float mu = s * (1.0f / Cc);
    float var = 0.f;
    #pragma unroll
    for (int i = 0; i < 16; i++) { float d = v[i] - mu; var += d * d; }
    #pragma unroll
    for (int off = 16; off > 0; off >>= 1) var += __shfl_xor_sync(0xFFFFFFFFu, var, off);
    var *= (1.0f / Cc);
    float r = rsqrtf(var + 1e-5f);
    #pragma unroll
    for (int i = 0; i < 16; i++) {
        int c = lane + 32*i;
        float o = (v[i] - mu) * r * gamma[c] + beta[c];
        xr[c] = o;
        xh[c] = __float2half_rn(o);
    }
}

// ---------------- logits: (NT,512) @ (512,65) + b  (full fp32) ---------------------
__global__ void __launch_bounds__(256)
logits_kernel(const float* __restrict__ lmw, const float* __restrict__ lmb,
              float* __restrict__ out) {
    __shared__ float As2[16][512];
    size_t row0 = (size_t)blockIdx.x * 16;
    for (int i = threadIdx.x; i < 16*512; i += 256)
        As2[i >> 9][i & 511] = g_x[(row0 + (i >> 9))*Cc + (i & 511)];
    __syncthreads();
    for (int idx2 = threadIdx.x; idx2 < 16*Vv; idx2 += 256) {
        int r = idx2 / Vv, c = idx2 % Vv;
        float s = lmb[c];
        #pragma unroll 8
        for (int k = 0; k < 512; k++) s += As2[r][k] * lmw[k*Vv + c];
        out[(row0 + r)*Vv + c] = s;
    }
}

// ---------------- host launch ------------------------------------------------------
extern "C" void kernel_launch(void* const* d_in, const int* in_sizes, int n_in,
                              void* d_out, int out_size) {
    const int*   idx    = (const int*)  d_in[0];
    const float* tok    = (const float*)d_in[1];
    const float* pos    = (const float*)d_in[2];
    const float* wq     = (const float*)d_in[3];
    const float* wk     = (const float*)d_in[4];
    const float* wv     = (const float*)d_in[5];
    const float* proj_w = (const float*)d_in[6];
    const float* proj_b = (const float*)d_in[7];
    const float* w1     = (const float*)d_in[8];
    const float* b1     = (const float*)d_in[9];
    const float* w2     = (const float*)d_in[10];
    const float* b2     = (const float*)d_in[11];
    const float* ln1g   = (const float*)d_in[12];
    const float* ln1b   = (const float*)d_in[13];
    const float* ln2g   = (const float*)d_in[14];
    const float* ln2b   = (const float*)d_in[15];
    const float* lm_w   = (const float*)d_in[16];
    const float* lm_b   = (const float*)d_in[17];
    float* out = (float*)d_out;

    cudaFuncSetAttribute(gemm_h, cudaFuncAttributeMaxDynamicSharedMemorySize, SMEM_DYN);

    float *x, *y;
    __half *xh, *qkvh, *aoh, *hh, *wqkvh, *wprojh, *w1h, *w2h;
    cudaGetSymbolAddress((void**)&x,     g_x);
    cudaGetSymbolAddress((void**)&xh,    g_xh);
    cudaGetSymbolAddress((void**)&qkvh,  g_qkvh);
    cudaGetSymbolAddress((void**)&aoh,   g_aoh);
    cudaGetSymbolAddress((void**)&y,     g_y);
    cudaGetSymbolAddress((void**)&hh,    g_hh);
    cudaGetSymbolAddress((void**)&wqkvh, g_wqkvh);
    cudaGetSymbolAddress((void**)&wprojh,g_wprojh);
    cudaGetSymbolAddress((void**)&w1h,   g_w1h);
    cudaGetSymbolAddress((void**)&w2h,   g_w2h);

    pack_qkv_h<<<(Ll*Cc*3*Cc + 255)/256, 256>>>(wq, wk, wv);
    half_copy<<<(Ll*Cc*Cc/2 + 255)/256, 256>>>(proj_w, wprojh, Ll*Cc*Cc/2);
    half_copy<<<(Ll*Cc*DFFd/2 + 255)/256, 256>>>(w1, w1h, Ll*Cc*DFFd/2);
    half_copy<<<(Ll*DFFd*Cc/2 + 255)/256, 256>>>(w2, w2h, Ll*DFFd*Cc/2);
    embed_kernel<<<(NT*Cc/4 + 255)/256, 256>>>(idx, tok, pos);

    for (int l = 0; l < Ll; l++) {
        // QKV: (NT,512)h @ (512,1536)h -> half
        gemm_h<<<dim3(3*Cc/BN, NT/BM), 256, SMEM_DYN>>>(
            xh, wqkvh + (size_t)l*Cc*3*Cc, nullptr, nullptr, qkvh, NT, 3*Cc, Cc, 0);
        // attention -> half ao
        attn_kernel<<<Bb*Hh/4, 128>>>();
        // proj: (NT,512)h @ (512,512)h + b -> fp32 y
        gemm_h<<<dim3(Cc/BN, NT/BM), 256, SMEM_DYN>>>(
            aoh, wprojh + (size_t)l*Cc*Cc, proj_b + (size_t)l*Cc, y, nullptr, NT, Cc, Cc, 0);
        // x = LN(x + y); writes fp32 + half
        add_ln_kernel<<<NT/8, 256>>>(y, ln1g + (size_t)l*Cc, ln1b + (size_t)l*Cc);
        // MLP up: (NT,512)h @ (512,2048)h + b, relu -> half h
        gemm_h<<<dim3(DFFd/BN, NT/BM), 256, SMEM_DYN>>>(
            xh, w1h + (size_t)l*Cc*DFFd, b1 + (size_t)l*DFFd, nullptr, hh, NT, DFFd, Cc, 1);
        // MLP down: (NT,2048)h @ (2048,512)h + b -> fp32 y
        gemm_h<<<dim3(Cc/BN, NT/BM), 256, SMEM_DYN>>>(
            hh, w2h + (size_t)l*DFFd*Cc, b2 + (size_t)l*Cc, y, nullptr, NT, Cc, DFFd, 0);
        // x = LN(x + y)
        add_ln_kernel<<<NT/8, 256>>>(y, ln2g + (size_t)l*Cc, ln2b + (size_t)l*Cc);
    }

    logits_kernel<<<NT/16, 256>>>(lm_w, lm_b, out);
}